// round 15
// baseline (speedup 1.0000x reference)
#include <cuda_runtime.h>
#include <cuda_fp16.h>
#include <cstdint>

#define BB 2
#define TT 2048
#define CC 1024
#define HH 16
#define HDIM 64
#define MTOT (BB * TT)   // 4096 rows total

// fp32 scratch
__device__ float g_bc[3 * CC];
// fp16 scratch
__device__ __half g_xh[MTOT * CC];
__device__ __half g_qh[MTOT * CC];
__device__ __half g_kh[MTOT * CC];
__device__ __half g_vh[MTOT * CC];     // V fp16, [token][C] (trans-loaded in attn)
__device__ __half g_ah[MTOT * CC];
__device__ __half g_wch[3 * CC * CC];  // combined QKV Wt [3072,1024]
__device__ __half g_wph[CC * CC];

// ---------------------------------------------------------------------------
// Helpers (base-target only: mma.sync + ldmatrix(+trans) + cp.async)
// ---------------------------------------------------------------------------
__device__ __forceinline__ uint32_t smem_u32(const void* p) {
    uint32_t a;
    asm("{ .reg .u64 t; cvta.to.shared.u64 t, %1; cvt.u32.u64 %0, t; }"
        : "=r"(a) : "l"(p));
    return a;
}
__device__ __forceinline__ uint32_t sw128(uint32_t off) {
    return off ^ ((off >> 3) & 0x70);
}
#define LDSM4(r, addr) \
    asm volatile("ldmatrix.sync.aligned.m8n8.x4.shared.b16 {%0,%1,%2,%3}, [%4];" \
        : "=r"((r)[0]), "=r"((r)[1]), "=r"((r)[2]), "=r"((r)[3]) : "r"(addr))
#define LDSM4T(r, addr) \
    asm volatile("ldmatrix.sync.aligned.m8n8.x4.trans.shared.b16 {%0,%1,%2,%3}, [%4];" \
        : "=r"((r)[0]), "=r"((r)[1]), "=r"((r)[2]), "=r"((r)[3]) : "r"(addr))
#define CP16(dst, src) \
    asm volatile("cp.async.cg.shared.global [%0], [%1], 16;" \
                 :: "r"(dst), "l"(src))
#define CP_COMMIT() asm volatile("cp.async.commit_group;" ::: "memory")
#define CP_WAIT2() asm volatile("cp.async.wait_group 2;" ::: "memory")
#define CP_WAIT1() asm volatile("cp.async.wait_group 1;" ::: "memory")
#define CP_WAIT0() asm volatile("cp.async.wait_group 0;" ::: "memory")

// fp32-accumulator MMA (half-rate)
__device__ __forceinline__ void mma16816(float* d, const uint32_t* a,
                                         const uint32_t* b) {
    asm volatile(
        "mma.sync.aligned.m16n8k16.row.col.f32.f16.f16.f32 "
        "{%0,%1,%2,%3}, {%4,%5,%6,%7}, {%8,%9}, {%0,%1,%2,%3};"
        : "+f"(d[0]), "+f"(d[1]), "+f"(d[2]), "+f"(d[3])
        : "r"(a[0]), "r"(a[1]), "r"(a[2]), "r"(a[3]), "r"(b[0]), "r"(b[1]));
}
// fp16-accumulator MMA (full-rate); D/C = 2 regs (4 halves, same c0..c3 map)
__device__ __forceinline__ void mma16816h(uint32_t& d0, uint32_t& d1,
                                          const uint32_t* a, const uint32_t* b) {
    asm volatile(
        "mma.sync.aligned.m16n8k16.row.col.f16.f16.f16.f16 "
        "{%0,%1}, {%2,%3,%4,%5}, {%6,%7}, {%0,%1};"
        : "+r"(d0), "+r"(d1)
        : "r"(a[0]), "r"(a[1]), "r"(a[2]), "r"(a[3]), "r"(b[0]), "r"(b[1]));
}

__device__ __forceinline__ uint32_t packh(float a, float b) {
    __half2 t = __floats2half2_rn(a, b);
    return *reinterpret_cast<uint32_t*>(&t);
}
__device__ __forceinline__ float2 unpackh(uint32_t u) {
    __half2 h = *reinterpret_cast<__half2*>(&u);
    return __half22float2(h);
}

// fast 2^u, clamped to [-30, 14] (fp16-safe upper bound; FMA-pipe polynomial)
__device__ __forceinline__ float fast_exp2c(float u) {
    u = fminf(fmaxf(u, -30.0f), 14.0f);
    float r = u + 12582912.0f;
    int n = __float_as_int(r) - 0x4B400000;
    float f = u - (r - 12582912.0f);
    float p = 0.00961813f;
    p = fmaf(p, f, 0.05550411f);
    p = fmaf(p, f, 0.24022651f);
    p = fmaf(p, f, 0.69314718f);
    p = fmaf(p, f, 1.0f);
    return p * __int_as_float((n + 127) << 23);
}

#define CEXP 0.18033688f   // 0.125 * log2(e)

// ---------------------------------------------------------------------------
// Fused pre-pass: z<4 -> weight transpose; z==4 -> x convert + bias cat
// ---------------------------------------------------------------------------
__global__ void __launch_bounds__(256) cvt_pre(
    const float* __restrict__ x,
    const float* __restrict__ W0, const float* __restrict__ W1,
    const float* __restrict__ W2, const float* __restrict__ W3,
    const float* __restrict__ bq, const float* __restrict__ bk,
    const float* __restrict__ bv,
    __half* __restrict__ xh, __half* __restrict__ Hc,
    __half* __restrict__ Hp, float* __restrict__ bc)
{
    const int z = blockIdx.z;
    const int tid = threadIdx.x;
    if (z == 4) {
        const int lin = blockIdx.x + 32 * blockIdx.y;
        const size_t base = (size_t)lin * 1024;   // in float4 units
        uint32_t* O = reinterpret_cast<uint32_t*>(xh);
        #pragma unroll
        for (int j = 0; j < 4; j++) {
            size_t i = base + tid + j * 256;
            float4 v = reinterpret_cast<const float4*>(x)[i];
            O[2 * i]     = packh(v.x, v.y);
            O[2 * i + 1] = packh(v.z, v.w);
        }
        if (lin == 0) {
            for (int t = tid; t < 3 * CC; t += 256)
                bc[t] = (t < CC) ? bq[t] : (t < 2 * CC) ? bk[t - CC]
                                                        : bv[t - 2 * CC];
        }
        return;
    }
    __shared__ float t[32][33];
    const float* W = (z == 0) ? W0 : (z == 1) ? W1 : (z == 2) ? W2 : W3;
    __half* Th = (z < 3) ? Hc + (size_t)z * CC * CC : Hp;
    const int bx = blockIdx.x * 32;   // n base
    const int by = blockIdx.y * 32;   // k base
    const int tx = tid & 31, ty = tid >> 5;
    #pragma unroll
    for (int i = 0; i < 4; i++)
        t[ty + i * 8][tx] = W[(size_t)(by + ty + i * 8) * CC + bx + tx];
    __syncthreads();
    #pragma unroll
    for (int i = 0; i < 4; i++) {
        float v = t[tx][ty + i * 8];
        size_t o = (size_t)(bx + ty + i * 8) * CC + by + tx;
        Th[o] = __float2half_rn(v);
    }
}

// ---------------------------------------------------------------------------
// Fused QKV GEMM. Tile 256x128, warp 64x64, 4-stage cp.async.
// Full-rate fp16-accumulator MMA, chained over one K=64 chunk per
// accumulator, then converted+added to persistent fp32 accumulators.
// ---------------------------------------------------------------------------
#define GK 1024
#define KC 64
#define NCHUNK (GK / KC)
#define QSTAGE 49152              // A 32KB + B 16KB
#define QKV_SMEM (4 * QSTAGE)     // 196608

__global__ void __launch_bounds__(256, 1)
qkv_gemm(const __half* __restrict__ A, const __half* __restrict__ Bh,
         const float* __restrict__ bias, __half* __restrict__ Qo,
         __half* __restrict__ Ko, __half* __restrict__ Vo)
{
    extern __shared__ __align__(128) char dsm[];
    const uint32_t sbase = smem_u32(dsm);

    const int tid = threadIdx.x;
    const int wid = tid >> 5, lane = tid & 31;
    const int g = lane >> 2, tig = lane & 3;
    const int wm = wid & 3, wn = wid >> 2;     // 4 x 2 warp grid
    const int m0 = blockIdx.y * 256;
    const int n0 = blockIdx.x * 128;

    const int laneA_row = ((lane >> 3) & 1) * 8 + (lane & 7);
    const int laneA_k   = ((lane >> 4) & 1) * 16;
    const int laneB_row = ((lane >> 4) & 1) * 8 + (lane & 7);
    const int laneB_k   = ((lane >> 3) & 1) * 16;

    float acc[4][8][4];
    #pragma unroll
    for (int mi = 0; mi < 4; mi++)
        #pragma unroll
        for (int ni = 0; ni < 8; ni++)
            #pragma unroll
            for (int r = 0; r < 4; r++) acc[mi][ni][r] = 0.0f;

    auto load_stage = [&](int c) {
        const uint32_t st = sbase + (c & 3) * QSTAGE;
        const int kb = c * KC;
        #pragma unroll
        for (int i = 0; i < 8; i++) {
            int id = tid + i * 256;
            int r = id >> 3, off = (id & 7) << 4;
            uint32_t so = sw128((uint32_t)(r << 7) + off);
            CP16(st + so, (const char*)(A + (size_t)(m0 + r) * GK + kb) + off);
        }
        #pragma unroll
        for (int i = 0; i < 4; i++) {
            int id = tid + i * 256;
            int r = id >> 3, off = (id & 7) << 4;
            uint32_t so = sw128((uint32_t)(r << 7) + off);
            CP16(st + 32768 + so,
                 (const char*)(Bh + (size_t)(n0 + r) * GK + kb) + off);
        }
        CP_COMMIT();
    };

    load_stage(0);
    load_stage(1);
    load_stage(2);

    for (int c = 0; c < NCHUNK; c++) {
        const int ahead = NCHUNK - 1 - c;
        if (ahead >= 2) CP_WAIT2();
        else if (ahead == 1) CP_WAIT1();
        else CP_WAIT0();
        __syncthreads();

        if (c + 3 < NCHUNK) load_stage(c + 3);

        const uint32_t st = sbase + (c & 3) * QSTAGE;
        const uint32_t sA = st, sB = st + 32768;

        // np-pair outer loop keeps fp16 chain temps transient (reg-safe)
        #pragma unroll
        for (int npp = 0; npp < 2; npp++) {
            uint32_t bf[2][4][4];
            #pragma unroll
            for (int j = 0; j < 2; j++)
                #pragma unroll
                for (int ks = 0; ks < 4; ks++) {
                    uint32_t boff = (uint32_t)((wn * 64 + (2 * npp + j) * 16
                                     + laneB_row) << 7) + ks * 32 + laneB_k;
                    LDSM4(bf[j][ks], sB + sw128(boff));
                }
            #pragma unroll
            for (int mi = 0; mi < 4; mi++) {
                uint32_t af[4][4];
                #pragma unroll
                for (int ks = 0; ks < 4; ks++) {
                    uint32_t aoff = (uint32_t)((wm * 64 + mi * 16 + laneA_row) << 7)
                                    + ks * 32 + laneA_k;
                    LDSM4(af[ks], sA + sw128(aoff));
                }
                #pragma unroll
                for (int j = 0; j < 2; j++)
                    #pragma unroll
                    for (int half = 0; half < 2; half++) {
                        uint32_t h0 = 0, h1 = 0;     // fp16 acc = +0
                        #pragma unroll
                        for (int ks = 0; ks < 4; ks++)
                            mma16816h(h0, h1, af[ks], &bf[j][ks][2 * half]);
                        const int ni = (2 * npp + j) * 2 + half;
                        float2 fa = unpackh(h0), fb = unpackh(h1);
                        acc[mi][ni][0] += fa.x;
                        acc[mi][ni][1] += fa.y;
                        acc[mi][ni][2] += fb.x;
                        acc[mi][ni][3] += fb.y;
                    }
            }
        }
    }

    // ---- epilogue: all sections fp16 ----
    const int nsec = n0 >> 10;
    __half* P = (nsec == 0) ? Qo : (nsec == 1) ? Ko : Vo;
    #pragma unroll
    for (int mi = 0; mi < 4; mi++) {
        const int row = m0 + wm * 64 + mi * 16 + g;
        #pragma unroll
        for (int ni = 0; ni < 8; ni++) {
            const int gcol = n0 + wn * 64 + ni * 8 + tig * 2;
            const float b0 = bias[gcol], b1 = bias[gcol + 1];
            const int col = gcol & 1023;
            *reinterpret_cast<uint32_t*>(P + (size_t)row * CC + col) =
                packh(acc[mi][ni][0] + b0, acc[mi][ni][1] + b1);
            *reinterpret_cast<uint32_t*>(P + (size_t)(row + 8) * CC + col) =
                packh(acc[mi][ni][2] + b0, acc[mi][ni][3] + b1);
        }
    }
}

// ---------------------------------------------------------------------------
// Proj GEMM: fp32-acc single-product, tile 128x128, warp 64x32, 3-stage, occ 2.
// ---------------------------------------------------------------------------
#define PSTAGE 32768              // A 16K + B 16K
#define PROJ_SMEM (3 * PSTAGE)    // 98304

__global__ void __launch_bounds__(256, 2)
proj_gemm(const __half* __restrict__ A, const __half* __restrict__ Bh,
          const float* __restrict__ bias, float* __restrict__ Cf)
{
    extern __shared__ __align__(128) char dsm[];
    const uint32_t sbase = smem_u32(dsm);

    const int tid = threadIdx.x;
    const int wid = tid >> 5, lane = tid & 31;
    const int g = lane >> 2, tig = lane & 3;
    const int wm = wid & 1, wn = wid >> 1;     // 2 x 4 warp grid
    const int m0 = blockIdx.y * 128;
    const int n0 = blockIdx.x * 128;

    const int laneA_row = ((lane >> 3) & 1) * 8 + (lane & 7);
    const int laneA_k   = ((lane >> 4) & 1) * 16;
    const int laneB_row = ((lane >> 4) & 1) * 8 + (lane & 7);
    const int laneB_k   = ((lane >> 3) & 1) * 16;

    float acc[4][4][4];
    #pragma unroll
    for (int mi = 0; mi < 4; mi++)
        #pragma unroll
        for (int ni = 0; ni < 4; ni++)
            #pragma unroll
            for (int r = 0; r < 4; r++) acc[mi][ni][r] = 0.0f;

    auto load_stage = [&](int c) {
        const uint32_t st = sbase + (c % 3) * PSTAGE;
        const int kb = c * KC;
        #pragma unroll
        for (int i = 0; i < 4; i++) {
            int id = tid + i * 256;
            int r = id >> 3, off = (id & 7) << 4;
            uint32_t so = sw128((uint32_t)(r << 7) + off);
            CP16(st + so,         (const char*)(A  + (size_t)(m0 + r) * GK + kb) + off);
            CP16(st + 16384 + so, (const char*)(Bh + (size_t)(n0 + r) * GK + kb) + off);
        }
        CP_COMMIT();
    };

    load_stage(0);
    load_stage(1);
    load_stage(2);

    for (int c = 0; c < NCHUNK; c++) {
        const int ahead = NCHUNK - 1 - c;
        if (ahead >= 2) CP_WAIT2();
        else if (ahead == 1) CP_WAIT1();
        else CP_WAIT0();
        __syncthreads();

        const uint32_t st = sbase + (c % 3) * PSTAGE;
        const uint32_t sA = st, sB = st + 16384;

        #pragma unroll
        for (int ks = 0; ks < 4; ks++) {
            uint32_t a[4][4];
            #pragma unroll
            for (int mi = 0; mi < 4; mi++) {
                uint32_t off = (uint32_t)((wm * 64 + mi * 16 + laneA_row) << 7)
                               + ks * 32 + laneA_k;
                LDSM4(a[mi], sA + sw128(off));
            }
            #pragma unroll
            for (int np = 0; np < 2; np++) {
                uint32_t boff = (uint32_t)((wn * 32 + np * 16 + laneB_row) << 7)
                                + ks * 32 + laneB_k;
                uint32_t b[4];
                LDSM4(b, sB + sw128(boff));
                #pragma unroll
                for (int mi = 0; mi < 4; mi++) {
                    mma16816(acc[mi][2 * np],     a[mi], b);
                    mma16816(acc[mi][2 * np + 1], a[mi], b + 2);
                }
            }
        }
        __syncthreads();
        if (c + 3 < NCHUNK) load_stage(c + 3);
    }

    #pragma unroll
    for (int mi = 0; mi < 4; mi++) {
        const int row = m0 + wm * 64 + mi * 16 + g;
        #pragma unroll
        for (int ni = 0; ni < 4; ni++) {
            const int gcol = n0 + wn * 32 + ni * 8 + tig * 2;
            const float b0 = bias[gcol], b1 = bias[gcol + 1];
            *reinterpret_cast<float2*>(Cf + (size_t)row * CC + gcol) =
                make_float2(acc[mi][ni][0] + b0, acc[mi][ni][1] + b1);
            *reinterpret_cast<float2*>(Cf + (size_t)(row + 8) * CC + gcol) =
                make_float2(acc[mi][ni][2] + b0, acc[mi][ni][3] + b1);
        }
    }
}

// ---------------------------------------------------------------------------
// Tensorized flash attention, fixed-max softmax. S computed with FULL-RATE
// fp16-accumulator MMA (K=64 chain; converted to fp32 only at exp time).
// PV keeps fp32 accumulation. 3 KV stages, single barrier per tile.
// ---------------------------------------------------------------------------
#define ATT_STG 16384
#define ATT_SMEM (3 * ATT_STG + 16384)   // 65536

__global__ void __launch_bounds__(256, 2) attn_mma(
    const __half* __restrict__ Qh, const __half* __restrict__ Kh,
    const __half* __restrict__ Vh, __half* __restrict__ Oh)
{
    extern __shared__ __align__(128) char dsm[];
    const uint32_t sb = smem_u32(dsm);
    const uint32_t sQ = sb + 3 * ATT_STG;

    const int qt = gridDim.x - 1 - blockIdx.x;   // heavy tiles first
    const int h = blockIdx.y, b = blockIdx.z;
    const int tid = threadIdx.x, w = tid >> 5, lane = tid & 31;
    const int g = lane >> 2, tig = lane & 3;
    const int NT = 2 * qt + 2;
    const int qrow0 = qt * 128;
    const size_t rowbase = (size_t)b * TT;

    const int laneA_row = ((lane >> 3) & 1) * 8 + (lane & 7);
    const int laneA_k   = ((lane >> 4) & 1) * 16;
    const int laneB_row = ((lane >> 4) & 1) * 8 + (lane & 7);
    const int laneB_k   = ((lane >> 3) & 1) * 16;
    const int laneV_row = ((lane >> 3) & 1) * 8 + (lane & 7);
    const int laneV_col = ((lane >> 4) & 1) * 8;

    // ---- Q load (16KB) ----
    #pragma unroll
    for (int i = 0; i < 4; i++) {
        int q = tid + i * 256;
        int r = q >> 3, off = (q & 7) << 4;
        uint32_t so = sw128((uint32_t)(r << 7) + off);
        size_t gb = ((rowbase + qrow0 + r) * CC + (size_t)h * HDIM) * 2 + off;
        CP16(sQ + so, (const char*)Qh + gb);
    }
    CP_COMMIT();

    auto load_kv = [&](int jt) {
        const uint32_t st = sb + (jt % 3) * ATT_STG;
        const int kb = jt * 64;
        #pragma unroll
        for (int i = 0; i < 2; i++) {
            int id = tid + i * 256;
            int r = id >> 3, off = (id & 7) << 4;
            uint32_t so = sw128((uint32_t)(r << 7) + off);
            size_t gk = ((rowbase + kb + r) * CC + (size_t)h * HDIM) * 2 + off;
            CP16(st + so,        (const char*)Kh + gk);
            CP16(st + 8192 + so, (const char*)Vh + gk);
        }
        CP_COMMIT();
    };

    load_kv(0);
    load_kv(1);

    float l0 = 0.0f, l1 = 0.0f;   // per-lane partial row sums (reduced at end)
    float o[8][4];
    #pragma unroll
    for (int nd = 0; nd < 8; nd++)
        #pragma unroll
        for (int r = 0; r < 4; r++) o[nd][r] = 0.0f;

    uint32_t qf[4][4];
    const int wrow_min = qrow0 + w * 16;
    const int wrow_max = wrow_min + 15;

    #pragma unroll 1
    for (int jt = 0; jt < NT; jt++) {
        if (jt < NT - 1) CP_WAIT1(); else CP_WAIT0();
        __syncthreads();

        if (jt + 2 < NT) load_kv(jt + 2);

        if (jt == 0) {   // Q fragments: loop-invariant
            #pragma unroll
            for (int kf = 0; kf < 4; kf++) {
                uint32_t off = (uint32_t)((w * 16 + laneA_row) << 7)
                               + kf * 32 + laneA_k;
                LDSM4(qf[kf], sQ + sw128(off));
            }
        }

        const int kb = jt * 64;
        if (kb <= wrow_max) {
            const uint32_t sK = sb + (jt % 3) * ATT_STG;
            const uint32_t sV = sK + 8192;
            const bool full = (kb + 63 <= wrow_min);

            // ---- S = q K^T, fp16 accumulator chain over K=64 ----
            uint32_t sh[8][2];
            #pragma unroll
            for (int np = 0; np < 4; np++) {
                uint32_t bfr[4][4];
                #pragma unroll
                for (int kf = 0; kf < 4; kf++) {
                    uint32_t boff = (uint32_t)((np * 16 + laneB_row) << 7)
                                    + kf * 32 + laneB_k;
                    LDSM4(bfr[kf], sK + sw128(boff));
                }
                #pragma unroll
                for (int half = 0; half < 2; half++) {
                    uint32_t h0 = 0, h1 = 0;
                    #pragma unroll
                    for (int kf = 0; kf < 4; kf++)
                        mma16816h(h0, h1, qf[kf], &bfr[kf][2 * half]);
                    sh[2 * np + half][0] = h0;
                    sh[2 * np + half][1] = h1;
                }
            }

            // ---- cvt + mask + fixed-max softmax: P = exp2(s * CEXP) ----
            const int r0 = wrow_min + g, r1 = r0 + 8;
            uint32_t pa[4][4];
            #pragma unroll
            for (int kc = 0; kc < 4; kc++) {
                float2 fa = unpackh(sh[2 * kc][0]);      // r0: k0, k0+1
                float2 fb = unpackh(sh[2 * kc][1]);      // r1: k0, k0+1
                float2 fc = unpackh(sh[2 * kc + 1][0]);
                float2 fd = unpackh(sh[2 * kc + 1][1]);
                if (!full) {
                    const int k0 = kb + 2 * kc * 8 + tig * 2;
                    const int k1 = kb + (2 * kc + 1) * 8 + tig * 2;
                    if (k0 > r0)     fa.x = -1e30f;
                    if (k0 + 1 > r0) fa.y = -1e30f;
                    if (k0 > r1)     fb.x = -1e30f;
                    if (k0 + 1 > r1) fb.y = -1e30f;
                    if (k1 > r0)     fc.x = -1e30f;
                    if (k1 + 1 > r0) fc.y = -1e30f;
                    if (k1 > r1)     fd.x = -1e30f;
                    if (k1 + 1 > r1) fd.y = -1e30f;
                }
                float p00 = fast_exp2c(fa.x * CEXP);
                float p01 = fast_exp2c(fa.y * CEXP);
                float p02 = fast_exp2c(fb.x * CEXP);
                float p03 = fast_exp2c(fb.y * CEXP);
                float p10 = fast_exp2c(fc.x * CEXP);
                float p11 = fast_exp2c(fc.y * CEXP);
                float p12 = fast_exp2c(fd.x * CEXP);
                float p13 = fast_exp2c(fd.y * CEXP);
                l0 += (p00 + p01) + (p10 + p11);
                l1 += (p02 + p03) + (p12 + p13);
                pa[kc][0] = packh(p00, p01);
                pa[kc][1] = packh(p02, p03);
                pa[kc][2] = packh(p10, p11);
                pa[kc][3] = packh(p12, p13);
            }

            // ---- O += P V  (fp32 acc; V fragments via ldmatrix.trans) ----
            #pragma unroll
            for (int np = 0; np < 4; np++) {
                #pragma unroll
                for (int kc = 0; kc < 4; kc++) {
                    uint32_t boff = (uint32_t)((kc * 16 + laneV_row) << 7)
                                    + (np * 16 + laneV_col) * 2;
                    uint32_t vh[4];
                    LDSM4T(vh, sV + sw128(boff));
                    mma16816(o[2 * np],     pa[kc], vh);
                    mma16816(o[2 * np + 1], pa[kc], vh + 2);
                }
            }
        }
    }

    // ---- epilogue: reduce l across the 4 lanes of each row, normalize ----
    l0 += __shfl_xor_sync(0xffffffffu, l0, 1);
    l0 += __shfl_xor_sync(0xffffffffu, l0, 2);
    l1 += __shfl_xor_sync(0xffffffffu, l1, 1);
    l1 += __shfl_xor_sync(0xffffffffu, l1, 2);
    const float inv0 = __fdividef(1.0f, l0);
    const float inv1 = __fdividef(1.0f, l1);
    const size_t r0 = rowbase + wrow_min + g;
    #pragma unroll
    for (int nd = 0; nd < 8; nd++) {
        const int col = h * HDIM + nd * 8 + tig * 2;
        *reinterpret_cast<uint32_t*>(Oh + r0 * CC + col) =
            packh(o[nd][0] * inv0, o[nd][1] * inv0);
        *reinterpret_cast<uint32_t*>(Oh + (r0 + 8) * CC + col) =
            packh(o[nd][2] * inv1, o[nd][3] * inv1);
    }
}

// ---------------------------------------------------------------------------
// kernel_launch
// ---------------------------------------------------------------------------
extern "C" void kernel_launch(void* const* d_in, const int* in_sizes, int n_in,
                              void* d_out, int out_size) {
    const float* x  = (const float*)d_in[0];
    const float* Wq = (const float*)d_in[1];
    const float* bq = (const float*)d_in[2];
    const float* Wk = (const float*)d_in[3];
    const float* bk = (const float*)d_in[4];
    const float* Wv = (const float*)d_in[5];
    const float* bv = (const float*)d_in[6];
    const float* Wp = (const float*)d_in[7];
    const float* bp = (const float*)d_in[8];
    float* out = (float*)d_out;

    float* bc;
    cudaGetSymbolAddress((void**)&bc, g_bc);
    __half *xh, *qh, *kh, *vh, *ah, *wch, *wph;
    cudaGetSymbolAddress((void**)&xh, g_xh);
    cudaGetSymbolAddress((void**)&qh, g_qh);
    cudaGetSymbolAddress((void**)&kh, g_kh);
    cudaGetSymbolAddress((void**)&vh, g_vh);
    cudaGetSymbolAddress((void**)&ah, g_ah);
    cudaGetSymbolAddress((void**)&wch, g_wch);
    cudaGetSymbolAddress((void**)&wph, g_wph);

    cudaFuncSetAttribute(qkv_gemm,
                         cudaFuncAttributeMaxDynamicSharedMemorySize, QKV_SMEM);
    cudaFuncSetAttribute(proj_gemm,
                         cudaFuncAttributeMaxDynamicSharedMemorySize, PROJ_SMEM);
    cudaFuncSetAttribute(attn_mma,
                         cudaFuncAttributeMaxDynamicSharedMemorySize, ATT_SMEM);

    // fused pre-pass: weight transposes (z=0..3) + x convert + bias cat (z=4)
    cvt_pre<<<dim3(32, 32, 5), 256>>>(x, Wq, Wk, Wv, Wp, bq, bk, bv,
                                      xh, wch, wph, bc);

    // fused QKV GEMM: N = 3072, tiles 256x128
    dim3 gq(3 * CC / 128, MTOT / 256);        // (24, 16)
    qkv_gemm<<<gq, 256, QKV_SMEM>>>(xh, wch, bc, qh, kh, vh);

    attn_mma<<<dim3(TT / 128, HH, BB), 256, ATT_SMEM>>>(qh, kh, vh, ah);

    dim3 gp(CC / 128, MTOT / 128);            // (8, 32) = 256 CTAs, occ 2
    proj_gemm<<<gp, 256, PROJ_SMEM>>>(ah, wph, bp, out);
}

// round 16
// speedup vs baseline: 1.1638x; 1.1638x over previous
#include <cuda_runtime.h>
#include <cuda_fp16.h>
#include <cstdint>

#define BB 2
#define TT 2048
#define CC 1024
#define HH 16
#define HDIM 64
#define MTOT (BB * TT)   // 4096 rows total

// fp32 scratch
__device__ float g_bc[3 * CC];
// fp16 scratch
__device__ __half g_xh[MTOT * CC];
__device__ __half g_qh[MTOT * CC];
__device__ __half g_kh[MTOT * CC];
__device__ __half g_vh[MTOT * CC];     // V fp16, [token][C] (trans-loaded in attn)
__device__ __half g_ah[MTOT * CC];
__device__ __half g_wch[3 * CC * CC];  // combined QKV Wt [3072,1024]
__device__ __half g_wph[CC * CC];

// ---------------------------------------------------------------------------
// Helpers (base-target only: mma.sync + ldmatrix(+trans) + cp.async)
// ---------------------------------------------------------------------------
__device__ __forceinline__ uint32_t smem_u32(const void* p) {
    uint32_t a;
    asm("{ .reg .u64 t; cvta.to.shared.u64 t, %1; cvt.u32.u64 %0, t; }"
        : "=r"(a) : "l"(p));
    return a;
}
__device__ __forceinline__ uint32_t sw128(uint32_t off) {
    return off ^ ((off >> 3) & 0x70);
}
#define LDSM4(r, addr) \
    asm volatile("ldmatrix.sync.aligned.m8n8.x4.shared.b16 {%0,%1,%2,%3}, [%4];" \
        : "=r"((r)[0]), "=r"((r)[1]), "=r"((r)[2]), "=r"((r)[3]) : "r"(addr))
#define LDSM4T(r, addr) \
    asm volatile("ldmatrix.sync.aligned.m8n8.x4.trans.shared.b16 {%0,%1,%2,%3}, [%4];" \
        : "=r"((r)[0]), "=r"((r)[1]), "=r"((r)[2]), "=r"((r)[3]) : "r"(addr))
#define CP16(dst, src) \
    asm volatile("cp.async.cg.shared.global [%0], [%1], 16;" \
                 :: "r"(dst), "l"(src))
#define CP_COMMIT() asm volatile("cp.async.commit_group;" ::: "memory")
#define CP_WAIT2() asm volatile("cp.async.wait_group 2;" ::: "memory")
#define CP_WAIT1() asm volatile("cp.async.wait_group 1;" ::: "memory")
#define CP_WAIT0() asm volatile("cp.async.wait_group 0;" ::: "memory")

__device__ __forceinline__ void mma16816(float* d, const uint32_t* a,
                                         const uint32_t* b) {
    asm volatile(
        "mma.sync.aligned.m16n8k16.row.col.f32.f16.f16.f32 "
        "{%0,%1,%2,%3}, {%4,%5,%6,%7}, {%8,%9}, {%0,%1,%2,%3};"
        : "+f"(d[0]), "+f"(d[1]), "+f"(d[2]), "+f"(d[3])
        : "r"(a[0]), "r"(a[1]), "r"(a[2]), "r"(a[3]), "r"(b[0]), "r"(b[1]));
}

__device__ __forceinline__ uint32_t packh(float a, float b) {
    __half2 t = __floats2half2_rn(a, b);
    return *reinterpret_cast<uint32_t*>(&t);
}

// fast 2^u, clamped to [-30, 14] (fp16-safe upper bound; FMA-pipe polynomial)
__device__ __forceinline__ float fast_exp2c(float u) {
    u = fminf(fmaxf(u, -30.0f), 14.0f);
    float r = u + 12582912.0f;
    int n = __float_as_int(r) - 0x4B400000;
    float f = u - (r - 12582912.0f);
    float p = 0.00961813f;
    p = fmaf(p, f, 0.05550411f);
    p = fmaf(p, f, 0.24022651f);
    p = fmaf(p, f, 0.69314718f);
    p = fmaf(p, f, 1.0f);
    return p * __int_as_float((n + 127) << 23);
}

#define CEXP 0.18033688f   // 0.125 * log2(e)

// ---------------------------------------------------------------------------
// Fused pre-pass: z<4 -> weight transpose; z==4 -> x convert + bias cat
// ---------------------------------------------------------------------------
__global__ void __launch_bounds__(256) cvt_pre(
    const float* __restrict__ x,
    const float* __restrict__ W0, const float* __restrict__ W1,
    const float* __restrict__ W2, const float* __restrict__ W3,
    const float* __restrict__ bq, const float* __restrict__ bk,
    const float* __restrict__ bv,
    __half* __restrict__ xh, __half* __restrict__ Hc,
    __half* __restrict__ Hp, float* __restrict__ bc)
{
    const int z = blockIdx.z;
    const int tid = threadIdx.x;
    if (z == 4) {
        const int lin = blockIdx.x + 32 * blockIdx.y;
        const size_t base = (size_t)lin * 1024;   // in float4 units
        uint32_t* O = reinterpret_cast<uint32_t*>(xh);
        #pragma unroll
        for (int j = 0; j < 4; j++) {
            size_t i = base + tid + j * 256;
            float4 v = reinterpret_cast<const float4*>(x)[i];
            O[2 * i]     = packh(v.x, v.y);
            O[2 * i + 1] = packh(v.z, v.w);
        }
        if (lin == 0) {
            for (int t = tid; t < 3 * CC; t += 256)
                bc[t] = (t < CC) ? bq[t] : (t < 2 * CC) ? bk[t - CC]
                                                        : bv[t - 2 * CC];
        }
        return;
    }
    __shared__ float t[32][33];
    const float* W = (z == 0) ? W0 : (z == 1) ? W1 : (z == 2) ? W2 : W3;
    __half* Th = (z < 3) ? Hc + (size_t)z * CC * CC : Hp;
    const int bx = blockIdx.x * 32;   // n base
    const int by = blockIdx.y * 32;   // k base
    const int tx = tid & 31, ty = tid >> 5;
    #pragma unroll
    for (int i = 0; i < 4; i++)
        t[ty + i * 8][tx] = W[(size_t)(by + ty + i * 8) * CC + bx + tx];
    __syncthreads();
    #pragma unroll
    for (int i = 0; i < 4; i++) {
        float v = t[tx][ty + i * 8];
        size_t o = (size_t)(bx + ty + i * 8) * CC + by + tx;
        Th[o] = __float2half_rn(v);
    }
}

// ---------------------------------------------------------------------------
// Fused QKV GEMM, single-product fp16, fp32 acc. Tile 256x128, warp 64x64.
// 4-stage cp.async, one __syncthreads per chunk.
// ---------------------------------------------------------------------------
#define GK 1024
#define KC 64
#define NCHUNK (GK / KC)
#define QSTAGE 49152              // A 32KB + B 16KB
#define QKV_SMEM (4 * QSTAGE)     // 196608

__global__ void __launch_bounds__(256, 1)
qkv_gemm(const __half* __restrict__ A, const __half* __restrict__ Bh,
         const float* __restrict__ bias, __half* __restrict__ Qo,
         __half* __restrict__ Ko, __half* __restrict__ Vo)
{
    extern __shared__ __align__(128) char dsm[];
    const uint32_t sbase = smem_u32(dsm);

    const int tid = threadIdx.x;
    const int wid = tid >> 5, lane = tid & 31;
    const int g = lane >> 2, tig = lane & 3;
    const int wm = wid & 3, wn = wid >> 2;     // 4 x 2 warp grid
    const int m0 = blockIdx.y * 256;
    const int n0 = blockIdx.x * 128;

    const int laneA_row = ((lane >> 3) & 1) * 8 + (lane & 7);
    const int laneA_k   = ((lane >> 4) & 1) * 16;
    const int laneB_row = ((lane >> 4) & 1) * 8 + (lane & 7);
    const int laneB_k   = ((lane >> 3) & 1) * 16;

    float acc[4][8][4];
    #pragma unroll
    for (int mi = 0; mi < 4; mi++)
        #pragma unroll
        for (int ni = 0; ni < 8; ni++)
            #pragma unroll
            for (int r = 0; r < 4; r++) acc[mi][ni][r] = 0.0f;

    auto load_stage = [&](int c) {
        const uint32_t st = sbase + (c & 3) * QSTAGE;
        const int kb = c * KC;
        #pragma unroll
        for (int i = 0; i < 8; i++) {
            int id = tid + i * 256;
            int r = id >> 3, off = (id & 7) << 4;
            uint32_t so = sw128((uint32_t)(r << 7) + off);
            CP16(st + so, (const char*)(A + (size_t)(m0 + r) * GK + kb) + off);
        }
        #pragma unroll
        for (int i = 0; i < 4; i++) {
            int id = tid + i * 256;
            int r = id >> 3, off = (id & 7) << 4;
            uint32_t so = sw128((uint32_t)(r << 7) + off);
            CP16(st + 32768 + so,
                 (const char*)(Bh + (size_t)(n0 + r) * GK + kb) + off);
        }
        CP_COMMIT();
    };

    load_stage(0);
    load_stage(1);
    load_stage(2);

    for (int c = 0; c < NCHUNK; c++) {
        const int ahead = NCHUNK - 1 - c;
        if (ahead >= 2) CP_WAIT2();
        else if (ahead == 1) CP_WAIT1();
        else CP_WAIT0();
        __syncthreads();                       // single barrier per chunk

        if (c + 3 < NCHUNK) load_stage(c + 3); // stage (c-1)%4, freed above

        const uint32_t st = sbase + (c & 3) * QSTAGE;
        const uint32_t sA = st, sB = st + 32768;

        #pragma unroll
        for (int ks = 0; ks < 4; ks++) {
            uint32_t a[4][4];
            #pragma unroll
            for (int mi = 0; mi < 4; mi++) {
                uint32_t off = (uint32_t)((wm * 64 + mi * 16 + laneA_row) << 7)
                               + ks * 32 + laneA_k;
                LDSM4(a[mi], sA + sw128(off));
            }
            #pragma unroll
            for (int np = 0; np < 4; np++) {
                uint32_t boff = (uint32_t)((wn * 64 + np * 16 + laneB_row) << 7)
                                + ks * 32 + laneB_k;
                uint32_t b[4];
                LDSM4(b, sB + sw128(boff));
                #pragma unroll
                for (int mi = 0; mi < 4; mi++) {
                    mma16816(acc[mi][2 * np],     a[mi], b);
                    mma16816(acc[mi][2 * np + 1], a[mi], b + 2);
                }
            }
        }
    }

    // ---- epilogue: all sections fp16 ----
    const int nsec = n0 >> 10;
    __half* P = (nsec == 0) ? Qo : (nsec == 1) ? Ko : Vo;
    #pragma unroll
    for (int mi = 0; mi < 4; mi++) {
        const int row = m0 + wm * 64 + mi * 16 + g;
        #pragma unroll
        for (int ni = 0; ni < 8; ni++) {
            const int gcol = n0 + wn * 64 + ni * 8 + tig * 2;
            const float b0 = bias[gcol], b1 = bias[gcol + 1];
            const int col = gcol & 1023;
            *reinterpret_cast<uint32_t*>(P + (size_t)row * CC + col) =
                packh(acc[mi][ni][0] + b0, acc[mi][ni][1] + b1);
            *reinterpret_cast<uint32_t*>(P + (size_t)(row + 8) * CC + col) =
                packh(acc[mi][ni][2] + b0, acc[mi][ni][3] + b1);
        }
    }
}

// ---------------------------------------------------------------------------
// Proj GEMM: single-product fp16, fp32 acc, tile 128x128, 3-stage, occ 2.
// ---------------------------------------------------------------------------
#define PSTAGE 32768              // A 16K + B 16K
#define PROJ_SMEM (3 * PSTAGE)    // 98304

__global__ void __launch_bounds__(256, 2)
proj_gemm(const __half* __restrict__ A, const __half* __restrict__ Bh,
          const float* __restrict__ bias, float* __restrict__ Cf)
{
    extern __shared__ __align__(128) char dsm[];
    const uint32_t sbase = smem_u32(dsm);

    const int tid = threadIdx.x;
    const int wid = tid >> 5, lane = tid & 31;
    const int g = lane >> 2, tig = lane & 3;
    const int wm = wid & 1, wn = wid >> 1;     // 2 x 4 warp grid
    const int m0 = blockIdx.y * 128;
    const int n0 = blockIdx.x * 128;

    const int laneA_row = ((lane >> 3) & 1) * 8 + (lane & 7);
    const int laneA_k   = ((lane >> 4) & 1) * 16;
    const int laneB_row = ((lane >> 4) & 1) * 8 + (lane & 7);
    const int laneB_k   = ((lane >> 3) & 1) * 16;

    float acc[4][4][4];
    #pragma unroll
    for (int mi = 0; mi < 4; mi++)
        #pragma unroll
        for (int ni = 0; ni < 4; ni++)
            #pragma unroll
            for (int r = 0; r < 4; r++) acc[mi][ni][r] = 0.0f;

    auto load_stage = [&](int c) {
        const uint32_t st = sbase + (c % 3) * PSTAGE;
        const int kb = c * KC;
        #pragma unroll
        for (int i = 0; i < 4; i++) {
            int id = tid + i * 256;
            int r = id >> 3, off = (id & 7) << 4;
            uint32_t so = sw128((uint32_t)(r << 7) + off);
            CP16(st + so,         (const char*)(A  + (size_t)(m0 + r) * GK + kb) + off);
            CP16(st + 16384 + so, (const char*)(Bh + (size_t)(n0 + r) * GK + kb) + off);
        }
        CP_COMMIT();
    };

    load_stage(0);
    load_stage(1);
    load_stage(2);

    for (int c = 0; c < NCHUNK; c++) {
        const int ahead = NCHUNK - 1 - c;
        if (ahead >= 2) CP_WAIT2();
        else if (ahead == 1) CP_WAIT1();
        else CP_WAIT0();
        __syncthreads();

        const uint32_t st = sbase + (c % 3) * PSTAGE;
        const uint32_t sA = st, sB = st + 16384;

        #pragma unroll
        for (int ks = 0; ks < 4; ks++) {
            uint32_t a[4][4];
            #pragma unroll
            for (int mi = 0; mi < 4; mi++) {
                uint32_t off = (uint32_t)((wm * 64 + mi * 16 + laneA_row) << 7)
                               + ks * 32 + laneA_k;
                LDSM4(a[mi], sA + sw128(off));
            }
            #pragma unroll
            for (int np = 0; np < 2; np++) {
                uint32_t boff = (uint32_t)((wn * 32 + np * 16 + laneB_row) << 7)
                                + ks * 32 + laneB_k;
                uint32_t b[4];
                LDSM4(b, sB + sw128(boff));
                #pragma unroll
                for (int mi = 0; mi < 4; mi++) {
                    mma16816(acc[mi][2 * np],     a[mi], b);
                    mma16816(acc[mi][2 * np + 1], a[mi], b + 2);
                }
            }
        }
        __syncthreads();
        if (c + 3 < NCHUNK) load_stage(c + 3);
    }

    #pragma unroll
    for (int mi = 0; mi < 4; mi++) {
        const int row = m0 + wm * 64 + mi * 16 + g;
        #pragma unroll
        for (int ni = 0; ni < 4; ni++) {
            const int gcol = n0 + wn * 32 + ni * 8 + tig * 2;
            const float b0 = bias[gcol], b1 = bias[gcol + 1];
            *reinterpret_cast<float2*>(Cf + (size_t)row * CC + gcol) =
                make_float2(acc[mi][ni][0] + b0, acc[mi][ni][1] + b1);
            *reinterpret_cast<float2*>(Cf + (size_t)(row + 8) * CC + gcol) =
                make_float2(acc[mi][ni][2] + b0, acc[mi][ni][3] + b1);
        }
    }
}

// ---------------------------------------------------------------------------
// Tensorized flash attention, fixed-max softmax, fp32-acc MMA throughout.
// Softmax and PV interleaved at kc granularity: each kc block's exps feed
// its 8 PV MMAs immediately, exposing exp(kc+1) || PV(kc) overlap.
// 3 KV stages, single barrier per tile, persistent Q.
// ---------------------------------------------------------------------------
#define ATT_STG 16384
#define ATT_SMEM (3 * ATT_STG + 16384)   // 65536

__global__ void __launch_bounds__(256, 2) attn_mma(
    const __half* __restrict__ Qh, const __half* __restrict__ Kh,
    const __half* __restrict__ Vh, __half* __restrict__ Oh)
{
    extern __shared__ __align__(128) char dsm[];
    const uint32_t sb = smem_u32(dsm);
    const uint32_t sQ = sb + 3 * ATT_STG;

    const int qt = gridDim.x - 1 - blockIdx.x;   // heavy tiles first
    const int h = blockIdx.y, b = blockIdx.z;
    const int tid = threadIdx.x, w = tid >> 5, lane = tid & 31;
    const int g = lane >> 2, tig = lane & 3;
    const int NT = 2 * qt + 2;
    const int qrow0 = qt * 128;
    const size_t rowbase = (size_t)b * TT;

    const int laneA_row = ((lane >> 3) & 1) * 8 + (lane & 7);
    const int laneA_k   = ((lane >> 4) & 1) * 16;
    const int laneB_row = ((lane >> 4) & 1) * 8 + (lane & 7);
    const int laneB_k   = ((lane >> 3) & 1) * 16;
    const int laneV_row = ((lane >> 3) & 1) * 8 + (lane & 7);
    const int laneV_col = ((lane >> 4) & 1) * 8;

    // ---- Q load (16KB) ----
    #pragma unroll
    for (int i = 0; i < 4; i++) {
        int q = tid + i * 256;
        int r = q >> 3, off = (q & 7) << 4;
        uint32_t so = sw128((uint32_t)(r << 7) + off);
        size_t gb = ((rowbase + qrow0 + r) * CC + (size_t)h * HDIM) * 2 + off;
        CP16(sQ + so, (const char*)Qh + gb);
    }
    CP_COMMIT();

    auto load_kv = [&](int jt) {
        const uint32_t st = sb + (jt % 3) * ATT_STG;
        const int kb = jt * 64;
        #pragma unroll
        for (int i = 0; i < 2; i++) {
            int id = tid + i * 256;
            int r = id >> 3, off = (id & 7) << 4;
            uint32_t so = sw128((uint32_t)(r << 7) + off);
            size_t gk = ((rowbase + kb + r) * CC + (size_t)h * HDIM) * 2 + off;
            CP16(st + so,        (const char*)Kh + gk);
            CP16(st + 8192 + so, (const char*)Vh + gk);
        }
        CP_COMMIT();
    };

    load_kv(0);
    load_kv(1);

    float l0 = 0.0f, l1 = 0.0f;   // per-lane partial row sums (reduced at end)
    float o[8][4];
    #pragma unroll
    for (int nd = 0; nd < 8; nd++)
        #pragma unroll
        for (int r = 0; r < 4; r++) o[nd][r] = 0.0f;

    uint32_t qf[4][4];
    const int wrow_min = qrow0 + w * 16;
    const int wrow_max = wrow_min + 15;

    #pragma unroll 1
    for (int jt = 0; jt < NT; jt++) {
        if (jt < NT - 1) CP_WAIT1(); else CP_WAIT0();
        __syncthreads();                       // single barrier per tile

        if (jt + 2 < NT) load_kv(jt + 2);      // stage (jt-1)%3, freed above

        if (jt == 0) {   // Q fragments: loop-invariant
            #pragma unroll
            for (int kf = 0; kf < 4; kf++) {
                uint32_t off = (uint32_t)((w * 16 + laneA_row) << 7)
                               + kf * 32 + laneA_k;
                LDSM4(qf[kf], sQ + sw128(off));
            }
        }

        const int kb = jt * 64;
        if (kb <= wrow_max) {
            const uint32_t sK = sb + (jt % 3) * ATT_STG;
            const uint32_t sV = sK + 8192;
            const bool full = (kb + 63 <= wrow_min);

            float s[8][4];
            #pragma unroll
            for (int nf = 0; nf < 8; nf++)
                #pragma unroll
                for (int r = 0; r < 4; r++) s[nf][r] = 0.0f;

            // ---- S = q K^T ----
            #pragma unroll
            for (int np = 0; np < 4; np++) {
                #pragma unroll
                for (int kf = 0; kf < 4; kf++) {
                    uint32_t boff = (uint32_t)((np * 16 + laneB_row) << 7)
                                    + kf * 32 + laneB_k;
                    uint32_t bh[4];
                    LDSM4(bh, sK + sw128(boff));
                    mma16816(s[2 * np],     qf[kf], bh);
                    mma16816(s[2 * np + 1], qf[kf], bh + 2);
                }
            }

            // ---- causal mask ----
            if (!full) {
                const int r0 = wrow_min + g, r1 = r0 + 8;
                #pragma unroll
                for (int nf = 0; nf < 8; nf++) {
                    const int k0 = kb + nf * 8 + tig * 2;
                    if (k0 > r0)     s[nf][0] = -1e30f;
                    if (k0 + 1 > r0) s[nf][1] = -1e30f;
                    if (k0 > r1)     s[nf][2] = -1e30f;
                    if (k0 + 1 > r1) s[nf][3] = -1e30f;
                }
            }

            // ---- interleaved: softmax(kc) then its PV MMAs immediately ----
            #pragma unroll
            for (int kc = 0; kc < 4; kc++) {
                float p00 = fast_exp2c(s[2 * kc][0] * CEXP);
                float p01 = fast_exp2c(s[2 * kc][1] * CEXP);
                float p02 = fast_exp2c(s[2 * kc][2] * CEXP);
                float p03 = fast_exp2c(s[2 * kc][3] * CEXP);
                float p10 = fast_exp2c(s[2 * kc + 1][0] * CEXP);
                float p11 = fast_exp2c(s[2 * kc + 1][1] * CEXP);
                float p12 = fast_exp2c(s[2 * kc + 1][2] * CEXP);
                float p13 = fast_exp2c(s[2 * kc + 1][3] * CEXP);
                l0 += (p00 + p01) + (p10 + p11);
                l1 += (p02 + p03) + (p12 + p13);
                uint32_t pa[4];
                pa[0] = packh(p00, p01);
                pa[1] = packh(p02, p03);
                pa[2] = packh(p10, p11);
                pa[3] = packh(p12, p13);

                #pragma unroll
                for (int np = 0; np < 4; np++) {
                    uint32_t boff = (uint32_t)((kc * 16 + laneV_row) << 7)
                                    + (np * 16 + laneV_col) * 2;
                    uint32_t vh[4];
                    LDSM4T(vh, sV + sw128(boff));
                    mma16816(o[2 * np],     pa, vh);
                    mma16816(o[2 * np + 1], pa, vh + 2);
                }
            }
        }
    }

    // ---- epilogue: reduce l across the 4 lanes of each row, normalize ----
    l0 += __shfl_xor_sync(0xffffffffu, l0, 1);
    l0 += __shfl_xor_sync(0xffffffffu, l0, 2);
    l1 += __shfl_xor_sync(0xffffffffu, l1, 1);
    l1 += __shfl_xor_sync(0xffffffffu, l1, 2);
    const float inv0 = __fdividef(1.0f, l0);
    const float inv1 = __fdividef(1.0f, l1);
    const size_t r0 = rowbase + wrow_min + g;
    #pragma unroll
    for (int nd = 0; nd < 8; nd++) {
        const int col = h * HDIM + nd * 8 + tig * 2;
        *reinterpret_cast<uint32_t*>(Oh + r0 * CC + col) =
            packh(o[nd][0] * inv0, o[nd][1] * inv0);
        *reinterpret_cast<uint32_t*>(Oh + (r0 + 8) * CC + col) =
            packh(o[nd][2] * inv1, o[nd][3] * inv1);
    }
}

// ---------------------------------------------------------------------------
// kernel_launch
// ---------------------------------------------------------------------------
extern "C" void kernel_launch(void* const* d_in, const int* in_sizes, int n_in,
                              void* d_out, int out_size) {
    const float* x  = (const float*)d_in[0];
    const float* Wq = (const float*)d_in[1];
    const float* bq = (const float*)d_in[2];
    const float* Wk = (const float*)d_in[3];
    const float* bk = (const float*)d_in[4];
    const float* Wv = (const float*)d_in[5];
    const float* bv = (const float*)d_in[6];
    const float* Wp = (const float*)d_in[7];
    const float* bp = (const float*)d_in[8];
    float* out = (float*)d_out;

    float* bc;
    cudaGetSymbolAddress((void**)&bc, g_bc);
    __half *xh, *qh, *kh, *vh, *ah, *wch, *wph;
    cudaGetSymbolAddress((void**)&xh, g_xh);
    cudaGetSymbolAddress((void**)&qh, g_qh);
    cudaGetSymbolAddress((void**)&kh, g_kh);
    cudaGetSymbolAddress((void**)&vh, g_vh);
    cudaGetSymbolAddress((void**)&ah, g_ah);
    cudaGetSymbolAddress((void**)&wch, g_wch);
    cudaGetSymbolAddress((void**)&wph, g_wph);

    cudaFuncSetAttribute(qkv_gemm,
                         cudaFuncAttributeMaxDynamicSharedMemorySize, QKV_SMEM);
    cudaFuncSetAttribute(proj_gemm,
                         cudaFuncAttributeMaxDynamicSharedMemorySize, PROJ_SMEM);
    cudaFuncSetAttribute(attn_mma,
                         cudaFuncAttributeMaxDynamicSharedMemorySize, ATT_SMEM);

    // fused pre-pass: weight transposes (z=0..3) + x convert + bias cat (z=4)
    cvt_pre<<<dim3(32, 32, 5), 256>>>(x, Wq, Wk, Wv, Wp, bq, bk, bv,
                                      xh, wch, wph, bc);

    // fused QKV GEMM: N = 3072, tiles 256x128
    dim3 gq(3 * CC / 128, MTOT / 256);        // (24, 16)
    qkv_gemm<<<gq, 256, QKV_SMEM>>>(xh, wch, bc, qh, kh, vh);

    attn_mma<<<dim3(TT / 128, HH, BB), 256, ATT_SMEM>>>(qh, kh, vh, ah);

    dim3 gp(CC / 128, MTOT / 128);            // (8, 32) = 256 CTAs, occ 2
    proj_gemm<<<gp, 256, PROJ_SMEM>>>(ah, wph, bp, out);
}

// round 17
// speedup vs baseline: 1.2911x; 1.1094x over previous
#include <cuda_runtime.h>
#include <cuda_fp16.h>
#include <cstdint>

#define BB 2
#define TT 2048
#define CC 1024
#define HH 16
#define HDIM 64
#define MTOT (BB * TT)   // 4096 rows total

// fp32 scratch
__device__ float g_bc[3 * CC];
// fp16 scratch
__device__ __half g_xh[MTOT * CC];
__device__ __half g_qh[MTOT * CC];
__device__ __half g_kh[MTOT * CC];
__device__ __half g_vh[MTOT * CC];     // V fp16, [token][C] (trans-loaded in attn)
__device__ __half g_ah[MTOT * CC];
__device__ __half g_wch[3 * CC * CC];  // combined QKV Wt [3072,1024]
__device__ __half g_wph[CC * CC];

// ---------------------------------------------------------------------------
// Helpers (base-target only: mma.sync + ldmatrix(+trans) + cp.async)
// ---------------------------------------------------------------------------
__device__ __forceinline__ uint32_t smem_u32(const void* p) {
    uint32_t a;
    asm("{ .reg .u64 t; cvta.to.shared.u64 t, %1; cvt.u32.u64 %0, t; }"
        : "=r"(a) : "l"(p));
    return a;
}
__device__ __forceinline__ uint32_t sw128(uint32_t off) {
    return off ^ ((off >> 3) & 0x70);
}
#define LDSM4(r, addr) \
    asm volatile("ldmatrix.sync.aligned.m8n8.x4.shared.b16 {%0,%1,%2,%3}, [%4];" \
        : "=r"((r)[0]), "=r"((r)[1]), "=r"((r)[2]), "=r"((r)[3]) : "r"(addr))
#define LDSM4T(r, addr) \
    asm volatile("ldmatrix.sync.aligned.m8n8.x4.trans.shared.b16 {%0,%1,%2,%3}, [%4];" \
        : "=r"((r)[0]), "=r"((r)[1]), "=r"((r)[2]), "=r"((r)[3]) : "r"(addr))
#define CP16(dst, src) \
    asm volatile("cp.async.cg.shared.global [%0], [%1], 16;" \
                 :: "r"(dst), "l"(src))
#define CP_COMMIT() asm volatile("cp.async.commit_group;" ::: "memory")
#define CP_WAIT2() asm volatile("cp.async.wait_group 2;" ::: "memory")
#define CP_WAIT1() asm volatile("cp.async.wait_group 1;" ::: "memory")
#define CP_WAIT0() asm volatile("cp.async.wait_group 0;" ::: "memory")

__device__ __forceinline__ void mma16816(float* d, const uint32_t* a,
                                         const uint32_t* b) {
    asm volatile(
        "mma.sync.aligned.m16n8k16.row.col.f32.f16.f16.f32 "
        "{%0,%1,%2,%3}, {%4,%5,%6,%7}, {%8,%9}, {%0,%1,%2,%3};"
        : "+f"(d[0]), "+f"(d[1]), "+f"(d[2]), "+f"(d[3])
        : "r"(a[0]), "r"(a[1]), "r"(a[2]), "r"(a[3]), "r"(b[0]), "r"(b[1]));
}

__device__ __forceinline__ uint32_t packh(float a, float b) {
    __half2 t = __floats2half2_rn(a, b);
    return *reinterpret_cast<uint32_t*>(&t);
}

// fast 2^u, clamped to [-30, 14] (fp16-safe upper bound; FMA-pipe polynomial)
__device__ __forceinline__ float fast_exp2c(float u) {
    u = fminf(fmaxf(u, -30.0f), 14.0f);
    float r = u + 12582912.0f;
    int n = __float_as_int(r) - 0x4B400000;
    float f = u - (r - 12582912.0f);
    float p = 0.00961813f;
    p = fmaf(p, f, 0.05550411f);
    p = fmaf(p, f, 0.24022651f);
    p = fmaf(p, f, 0.69314718f);
    p = fmaf(p, f, 1.0f);
    return p * __int_as_float((n + 127) << 23);
}

#define CEXP 0.18033688f   // 0.125 * log2(e)

// ---------------------------------------------------------------------------
// Fused pre-pass: z<4 -> weight transpose; z==4 -> x convert + bias cat
// ---------------------------------------------------------------------------
__global__ void __launch_bounds__(256) cvt_pre(
    const float* __restrict__ x,
    const float* __restrict__ W0, const float* __restrict__ W1,
    const float* __restrict__ W2, const float* __restrict__ W3,
    const float* __restrict__ bq, const float* __restrict__ bk,
    const float* __restrict__ bv,
    __half* __restrict__ xh, __half* __restrict__ Hc,
    __half* __restrict__ Hp, float* __restrict__ bc)
{
    const int z = blockIdx.z;
    const int tid = threadIdx.x;
    if (z == 4) {
        const int lin = blockIdx.x + 32 * blockIdx.y;
        const size_t base = (size_t)lin * 1024;   // in float4 units
        uint32_t* O = reinterpret_cast<uint32_t*>(xh);
        #pragma unroll
        for (int j = 0; j < 4; j++) {
            size_t i = base + tid + j * 256;
            float4 v = reinterpret_cast<const float4*>(x)[i];
            O[2 * i]     = packh(v.x, v.y);
            O[2 * i + 1] = packh(v.z, v.w);
        }
        if (lin == 0) {
            for (int t = tid; t < 3 * CC; t += 256)
                bc[t] = (t < CC) ? bq[t] : (t < 2 * CC) ? bk[t - CC]
                                                        : bv[t - 2 * CC];
        }
        return;
    }
    __shared__ float t[32][33];
    const float* W = (z == 0) ? W0 : (z == 1) ? W1 : (z == 2) ? W2 : W3;
    __half* Th = (z < 3) ? Hc + (size_t)z * CC * CC : Hp;
    const int bx = blockIdx.x * 32;   // n base
    const int by = blockIdx.y * 32;   // k base
    const int tx = tid & 31, ty = tid >> 5;
    #pragma unroll
    for (int i = 0; i < 4; i++)
        t[ty + i * 8][tx] = W[(size_t)(by + ty + i * 8) * CC + bx + tx];
    __syncthreads();
    #pragma unroll
    for (int i = 0; i < 4; i++) {
        float v = t[tx][ty + i * 8];
        size_t o = (size_t)(bx + ty + i * 8) * CC + by + tx;
        Th[o] = __float2half_rn(v);
    }
}

// ---------------------------------------------------------------------------
// Fused QKV GEMM, single-product fp16, fp32 acc. Tile 256x128, warp 64x64.
// 4-stage cp.async, one __syncthreads per chunk.
// ---------------------------------------------------------------------------
#define GK 1024
#define KC 64
#define NCHUNK (GK / KC)
#define QSTAGE 49152              // A 32KB + B 16KB
#define QKV_SMEM (4 * QSTAGE)     // 196608

__global__ void __launch_bounds__(256, 1)
qkv_gemm(const __half* __restrict__ A, const __half* __restrict__ Bh,
         const float* __restrict__ bias, __half* __restrict__ Qo,
         __half* __restrict__ Ko, __half* __restrict__ Vo)
{
    extern __shared__ __align__(128) char dsm[];
    const uint32_t sbase = smem_u32(dsm);

    const int tid = threadIdx.x;
    const int wid = tid >> 5, lane = tid & 31;
    const int g = lane >> 2, tig = lane & 3;
    const int wm = wid & 3, wn = wid >> 2;     // 4 x 2 warp grid
    const int m0 = blockIdx.y * 256;
    const int n0 = blockIdx.x * 128;

    const int laneA_row = ((lane >> 3) & 1) * 8 + (lane & 7);
    const int laneA_k   = ((lane >> 4) & 1) * 16;
    const int laneB_row = ((lane >> 4) & 1) * 8 + (lane & 7);
    const int laneB_k   = ((lane >> 3) & 1) * 16;

    float acc[4][8][4];
    #pragma unroll
    for (int mi = 0; mi < 4; mi++)
        #pragma unroll
        for (int ni = 0; ni < 8; ni++)
            #pragma unroll
            for (int r = 0; r < 4; r++) acc[mi][ni][r] = 0.0f;

    auto load_stage = [&](int c) {
        const uint32_t st = sbase + (c & 3) * QSTAGE;
        const int kb = c * KC;
        #pragma unroll
        for (int i = 0; i < 8; i++) {
            int id = tid + i * 256;
            int r = id >> 3, off = (id & 7) << 4;
            uint32_t so = sw128((uint32_t)(r << 7) + off);
            CP16(st + so, (const char*)(A + (size_t)(m0 + r) * GK + kb) + off);
        }
        #pragma unroll
        for (int i = 0; i < 4; i++) {
            int id = tid + i * 256;
            int r = id >> 3, off = (id & 7) << 4;
            uint32_t so = sw128((uint32_t)(r << 7) + off);
            CP16(st + 32768 + so,
                 (const char*)(Bh + (size_t)(n0 + r) * GK + kb) + off);
        }
        CP_COMMIT();
    };

    load_stage(0);
    load_stage(1);
    load_stage(2);

    for (int c = 0; c < NCHUNK; c++) {
        const int ahead = NCHUNK - 1 - c;
        if (ahead >= 2) CP_WAIT2();
        else if (ahead == 1) CP_WAIT1();
        else CP_WAIT0();
        __syncthreads();                       // single barrier per chunk

        if (c + 3 < NCHUNK) load_stage(c + 3); // stage (c-1)%4, freed above

        const uint32_t st = sbase + (c & 3) * QSTAGE;
        const uint32_t sA = st, sB = st + 32768;

        #pragma unroll
        for (int ks = 0; ks < 4; ks++) {
            uint32_t a[4][4];
            #pragma unroll
            for (int mi = 0; mi < 4; mi++) {
                uint32_t off = (uint32_t)((wm * 64 + mi * 16 + laneA_row) << 7)
                               + ks * 32 + laneA_k;
                LDSM4(a[mi], sA + sw128(off));
            }
            #pragma unroll
            for (int np = 0; np < 4; np++) {
                uint32_t boff = (uint32_t)((wn * 64 + np * 16 + laneB_row) << 7)
                                + ks * 32 + laneB_k;
                uint32_t b[4];
                LDSM4(b, sB + sw128(boff));
                #pragma unroll
                for (int mi = 0; mi < 4; mi++) {
                    mma16816(acc[mi][2 * np],     a[mi], b);
                    mma16816(acc[mi][2 * np + 1], a[mi], b + 2);
                }
            }
        }
    }

    // ---- epilogue: all sections fp16 ----
    const int nsec = n0 >> 10;
    __half* P = (nsec == 0) ? Qo : (nsec == 1) ? Ko : Vo;
    #pragma unroll
    for (int mi = 0; mi < 4; mi++) {
        const int row = m0 + wm * 64 + mi * 16 + g;
        #pragma unroll
        for (int ni = 0; ni < 8; ni++) {
            const int gcol = n0 + wn * 64 + ni * 8 + tig * 2;
            const float b0 = bias[gcol], b1 = bias[gcol + 1];
            const int col = gcol & 1023;
            *reinterpret_cast<uint32_t*>(P + (size_t)row * CC + col) =
                packh(acc[mi][ni][0] + b0, acc[mi][ni][1] + b1);
            *reinterpret_cast<uint32_t*>(P + (size_t)(row + 8) * CC + col) =
                packh(acc[mi][ni][2] + b0, acc[mi][ni][3] + b1);
        }
    }
}

// ---------------------------------------------------------------------------
// Proj GEMM: single-product fp16, fp32 acc, tile 128x128, 3-stage, occ 2.
// ---------------------------------------------------------------------------
#define PSTAGE 32768              // A 16K + B 16K
#define PROJ_SMEM (3 * PSTAGE)    // 98304

__global__ void __launch_bounds__(256, 2)
proj_gemm(const __half* __restrict__ A, const __half* __restrict__ Bh,
          const float* __restrict__ bias, float* __restrict__ Cf)
{
    extern __shared__ __align__(128) char dsm[];
    const uint32_t sbase = smem_u32(dsm);

    const int tid = threadIdx.x;
    const int wid = tid >> 5, lane = tid & 31;
    const int g = lane >> 2, tig = lane & 3;
    const int wm = wid & 1, wn = wid >> 1;     // 2 x 4 warp grid
    const int m0 = blockIdx.y * 128;
    const int n0 = blockIdx.x * 128;

    const int laneA_row = ((lane >> 3) & 1) * 8 + (lane & 7);
    const int laneA_k   = ((lane >> 4) & 1) * 16;
    const int laneB_row = ((lane >> 4) & 1) * 8 + (lane & 7);
    const int laneB_k   = ((lane >> 3) & 1) * 16;

    float acc[4][4][4];
    #pragma unroll
    for (int mi = 0; mi < 4; mi++)
        #pragma unroll
        for (int ni = 0; ni < 4; ni++)
            #pragma unroll
            for (int r = 0; r < 4; r++) acc[mi][ni][r] = 0.0f;

    auto load_stage = [&](int c) {
        const uint32_t st = sbase + (c % 3) * PSTAGE;
        const int kb = c * KC;
        #pragma unroll
        for (int i = 0; i < 4; i++) {
            int id = tid + i * 256;
            int r = id >> 3, off = (id & 7) << 4;
            uint32_t so = sw128((uint32_t)(r << 7) + off);
            CP16(st + so,         (const char*)(A  + (size_t)(m0 + r) * GK + kb) + off);
            CP16(st + 16384 + so, (const char*)(Bh + (size_t)(n0 + r) * GK + kb) + off);
        }
        CP_COMMIT();
    };

    load_stage(0);
    load_stage(1);
    load_stage(2);

    for (int c = 0; c < NCHUNK; c++) {
        const int ahead = NCHUNK - 1 - c;
        if (ahead >= 2) CP_WAIT2();
        else if (ahead == 1) CP_WAIT1();
        else CP_WAIT0();
        __syncthreads();

        const uint32_t st = sbase + (c % 3) * PSTAGE;
        const uint32_t sA = st, sB = st + 16384;

        #pragma unroll
        for (int ks = 0; ks < 4; ks++) {
            uint32_t a[4][4];
            #pragma unroll
            for (int mi = 0; mi < 4; mi++) {
                uint32_t off = (uint32_t)((wm * 64 + mi * 16 + laneA_row) << 7)
                               + ks * 32 + laneA_k;
                LDSM4(a[mi], sA + sw128(off));
            }
            #pragma unroll
            for (int np = 0; np < 2; np++) {
                uint32_t boff = (uint32_t)((wn * 32 + np * 16 + laneB_row) << 7)
                                + ks * 32 + laneB_k;
                uint32_t b[4];
                LDSM4(b, sB + sw128(boff));
                #pragma unroll
                for (int mi = 0; mi < 4; mi++) {
                    mma16816(acc[mi][2 * np],     a[mi], b);
                    mma16816(acc[mi][2 * np + 1], a[mi], b + 2);
                }
            }
        }
        __syncthreads();
        if (c + 3 < NCHUNK) load_stage(c + 3);
    }

    #pragma unroll
    for (int mi = 0; mi < 4; mi++) {
        const int row = m0 + wm * 64 + mi * 16 + g;
        #pragma unroll
        for (int ni = 0; ni < 4; ni++) {
            const int gcol = n0 + wn * 32 + ni * 8 + tig * 2;
            const float b0 = bias[gcol], b1 = bias[gcol + 1];
            *reinterpret_cast<float2*>(Cf + (size_t)row * CC + gcol) =
                make_float2(acc[mi][ni][0] + b0, acc[mi][ni][1] + b1);
            *reinterpret_cast<float2*>(Cf + (size_t)(row + 8) * CC + gcol) =
                make_float2(acc[mi][ni][2] + b0, acc[mi][ni][3] + b1);
        }
    }
}

// ---------------------------------------------------------------------------
// Tensorized flash attention, fixed-max softmax, interleaved softmax/PV.
// PAIRED q-tiles: CTA i processes qt = 15-i then qt = i -> uniform 34
// key-tiles per CTA, 256 CTAs = one balanced wave at occ 2.
// 3 KV stages, single barrier per tile, Q reloaded per phase.
// ---------------------------------------------------------------------------
#define ATT_STG 16384
#define ATT_SMEM (3 * ATT_STG + 16384)   // 65536

__global__ void __launch_bounds__(256, 2) attn_mma(
    const __half* __restrict__ Qh, const __half* __restrict__ Kh,
    const __half* __restrict__ Vh, __half* __restrict__ Oh)
{
    extern __shared__ __align__(128) char dsm[];
    const uint32_t sb = smem_u32(dsm);
    const uint32_t sQ = sb + 3 * ATT_STG;

    const int pi = blockIdx.x;                   // 0..7
    const int h = blockIdx.y, b = blockIdx.z;
    const int tid = threadIdx.x, w = tid >> 5, lane = tid & 31;
    const int g = lane >> 2, tig = lane & 3;
    const size_t rowbase = (size_t)b * TT;

    const int laneA_row = ((lane >> 3) & 1) * 8 + (lane & 7);
    const int laneA_k   = ((lane >> 4) & 1) * 16;
    const int laneB_row = ((lane >> 4) & 1) * 8 + (lane & 7);
    const int laneB_k   = ((lane >> 3) & 1) * 16;
    const int laneV_row = ((lane >> 3) & 1) * 8 + (lane & 7);
    const int laneV_col = ((lane >> 4) & 1) * 8;

    #pragma unroll 1
    for (int ph = 0; ph < 2; ph++) {
        const int qt = ph ? pi : (15 - pi);      // heavy tile first
        const int NT = 2 * qt + 2;
        const int qrow0 = qt * 128;
        const int wrow_min = qrow0 + w * 16;
        const int wrow_max = wrow_min + 15;

        // ---- Q load (16KB) ----
        #pragma unroll
        for (int i = 0; i < 4; i++) {
            int q = tid + i * 256;
            int r = q >> 3, off = (q & 7) << 4;
            uint32_t so = sw128((uint32_t)(r << 7) + off);
            size_t gb = ((rowbase + qrow0 + r) * CC + (size_t)h * HDIM) * 2 + off;
            CP16(sQ + so, (const char*)Qh + gb);
        }
        CP_COMMIT();

        auto load_kv = [&](int jt) {
            const uint32_t st = sb + (jt % 3) * ATT_STG;
            const int kb = jt * 64;
            #pragma unroll
            for (int i = 0; i < 2; i++) {
                int id = tid + i * 256;
                int r = id >> 3, off = (id & 7) << 4;
                uint32_t so = sw128((uint32_t)(r << 7) + off);
                size_t gk = ((rowbase + kb + r) * CC + (size_t)h * HDIM) * 2 + off;
                CP16(st + so,        (const char*)Kh + gk);
                CP16(st + 8192 + so, (const char*)Vh + gk);
            }
            CP_COMMIT();
        };

        load_kv(0);
        load_kv(1);

        float l0 = 0.0f, l1 = 0.0f;
        float o[8][4];
        #pragma unroll
        for (int nd = 0; nd < 8; nd++)
            #pragma unroll
            for (int r = 0; r < 4; r++) o[nd][r] = 0.0f;

        uint32_t qf[4][4];

        #pragma unroll 1
        for (int jt = 0; jt < NT; jt++) {
            if (jt < NT - 1) CP_WAIT1(); else CP_WAIT0();
            __syncthreads();                    // single barrier per tile

            if (jt + 2 < NT) load_kv(jt + 2);   // stage (jt-1)%3, freed above

            if (jt == 0) {                      // Q fragments: phase-invariant
                #pragma unroll
                for (int kf = 0; kf < 4; kf++) {
                    uint32_t off = (uint32_t)((w * 16 + laneA_row) << 7)
                                   + kf * 32 + laneA_k;
                    LDSM4(qf[kf], sQ + sw128(off));
                }
            }

            const int kb = jt * 64;
            if (kb <= wrow_max) {
                const uint32_t sK = sb + (jt % 3) * ATT_STG;
                const uint32_t sV = sK + 8192;
                const bool full = (kb + 63 <= wrow_min);

                float s[8][4];
                #pragma unroll
                for (int nf = 0; nf < 8; nf++)
                    #pragma unroll
                    for (int r = 0; r < 4; r++) s[nf][r] = 0.0f;

                // ---- S = q K^T ----
                #pragma unroll
                for (int np = 0; np < 4; np++) {
                    #pragma unroll
                    for (int kf = 0; kf < 4; kf++) {
                        uint32_t boff = (uint32_t)((np * 16 + laneB_row) << 7)
                                        + kf * 32 + laneB_k;
                        uint32_t bh[4];
                        LDSM4(bh, sK + sw128(boff));
                        mma16816(s[2 * np],     qf[kf], bh);
                        mma16816(s[2 * np + 1], qf[kf], bh + 2);
                    }
                }

                // ---- causal mask ----
                if (!full) {
                    const int r0 = wrow_min + g, r1 = r0 + 8;
                    #pragma unroll
                    for (int nf = 0; nf < 8; nf++) {
                        const int k0 = kb + nf * 8 + tig * 2;
                        if (k0 > r0)     s[nf][0] = -1e30f;
                        if (k0 + 1 > r0) s[nf][1] = -1e30f;
                        if (k0 > r1)     s[nf][2] = -1e30f;
                        if (k0 + 1 > r1) s[nf][3] = -1e30f;
                    }
                }

                // ---- interleaved softmax(kc) + its PV MMAs ----
                #pragma unroll
                for (int kc = 0; kc < 4; kc++) {
                    float p00 = fast_exp2c(s[2 * kc][0] * CEXP);
                    float p01 = fast_exp2c(s[2 * kc][1] * CEXP);
                    float p02 = fast_exp2c(s[2 * kc][2] * CEXP);
                    float p03 = fast_exp2c(s[2 * kc][3] * CEXP);
                    float p10 = fast_exp2c(s[2 * kc + 1][0] * CEXP);
                    float p11 = fast_exp2c(s[2 * kc + 1][1] * CEXP);
                    float p12 = fast_exp2c(s[2 * kc + 1][2] * CEXP);
                    float p13 = fast_exp2c(s[2 * kc + 1][3] * CEXP);
                    l0 += (p00 + p01) + (p10 + p11);
                    l1 += (p02 + p03) + (p12 + p13);
                    uint32_t pa[4];
                    pa[0] = packh(p00, p01);
                    pa[1] = packh(p02, p03);
                    pa[2] = packh(p10, p11);
                    pa[3] = packh(p12, p13);

                    #pragma unroll
                    for (int np = 0; np < 4; np++) {
                        uint32_t boff = (uint32_t)((kc * 16 + laneV_row) << 7)
                                        + (np * 16 + laneV_col) * 2;
                        uint32_t vh[4];
                        LDSM4T(vh, sV + sw128(boff));
                        mma16816(o[2 * np],     pa, vh);
                        mma16816(o[2 * np + 1], pa, vh + 2);
                    }
                }
            }
        }

        // ---- epilogue: reduce l, normalize, store ----
        l0 += __shfl_xor_sync(0xffffffffu, l0, 1);
        l0 += __shfl_xor_sync(0xffffffffu, l0, 2);
        l1 += __shfl_xor_sync(0xffffffffu, l1, 1);
        l1 += __shfl_xor_sync(0xffffffffu, l1, 2);
        const float inv0 = __fdividef(1.0f, l0);
        const float inv1 = __fdividef(1.0f, l1);
        const size_t r0 = rowbase + wrow_min + g;
        #pragma unroll
        for (int nd = 0; nd < 8; nd++) {
            const int col = h * HDIM + nd * 8 + tig * 2;
            *reinterpret_cast<uint32_t*>(Oh + r0 * CC + col) =
                packh(o[nd][0] * inv0, o[nd][1] * inv0);
            *reinterpret_cast<uint32_t*>(Oh + (r0 + 8) * CC + col) =
                packh(o[nd][2] * inv1, o[nd][3] * inv1);
        }

        // all warps done with this phase's smem before phase 1 overwrites
        __syncthreads();
    }
}

// ---------------------------------------------------------------------------
// kernel_launch
// ---------------------------------------------------------------------------
extern "C" void kernel_launch(void* const* d_in, const int* in_sizes, int n_in,
                              void* d_out, int out_size) {
    const float* x  = (const float*)d_in[0];
    const float* Wq = (const float*)d_in[1];
    const float* bq = (const float*)d_in[2];
    const float* Wk = (const float*)d_in[3];
    const float* bk = (const float*)d_in[4];
    const float* Wv = (const float*)d_in[5];
    const float* bv = (const float*)d_in[6];
    const float* Wp = (const float*)d_in[7];
    const float* bp = (const float*)d_in[8];
    float* out = (float*)d_out;

    float* bc;
    cudaGetSymbolAddress((void**)&bc, g_bc);
    __half *xh, *qh, *kh, *vh, *ah, *wch, *wph;
    cudaGetSymbolAddress((void**)&xh, g_xh);
    cudaGetSymbolAddress((void**)&qh, g_qh);
    cudaGetSymbolAddress((void**)&kh, g_kh);
    cudaGetSymbolAddress((void**)&vh, g_vh);
    cudaGetSymbolAddress((void**)&ah, g_ah);
    cudaGetSymbolAddress((void**)&wch, g_wch);
    cudaGetSymbolAddress((void**)&wph, g_wph);

    cudaFuncSetAttribute(qkv_gemm,
                         cudaFuncAttributeMaxDynamicSharedMemorySize, QKV_SMEM);
    cudaFuncSetAttribute(proj_gemm,
                         cudaFuncAttributeMaxDynamicSharedMemorySize, PROJ_SMEM);
    cudaFuncSetAttribute(attn_mma,
                         cudaFuncAttributeMaxDynamicSharedMemorySize, ATT_SMEM);

    // fused pre-pass: weight transposes (z=0..3) + x convert + bias cat (z=4)
    cvt_pre<<<dim3(32, 32, 5), 256>>>(x, Wq, Wk, Wv, Wp, bq, bk, bv,
                                      xh, wch, wph, bc);

    // fused QKV GEMM: N = 3072, tiles 256x128
    dim3 gq(3 * CC / 128, MTOT / 256);        // (24, 16)
    qkv_gemm<<<gq, 256, QKV_SMEM>>>(xh, wch, bc, qh, kh, vh);

    // paired q-tiles: 8 x 16 x 2 = 256 CTAs, uniform 34 key-tiles each
    attn_mma<<<dim3(8, HH, BB), 256, ATT_SMEM>>>(qh, kh, vh, ah);

    dim3 gp(CC / 128, MTOT / 128);            // (8, 32) = 256 CTAs, occ 2
    proj_gemm<<<gp, 256, PROJ_SMEM>>>(ah, wph, bp, out);
}